// round 15
// baseline (speedup 1.0000x reference)
#include <cuda_runtime.h>
#include <cuda_bf16.h>
#include <math.h>

// ---------------------------------------------------------------------------
// POMO decoder v15 — v14 base; pointer warp tile 16x64 (8 independent MMA
// chains, LDSM:MMA 0.42, 8 gt iterations, reg-pipelined B).
// B=64, N=500, E=128, H=8, D=16
// ---------------------------------------------------------------------------

#define Bb 64
#define Nn 500
#define Hh 8
#define QKV_STRIDE 40

typedef unsigned long long ull;

__device__ unsigned g_maskbits[Bb * Nn * 16];
__device__ __nv_bfloat16 g_q_split[Bb * Hh * 512 * QKV_STRIDE];
__device__ __nv_bfloat16 g_k_split[Bb * Hh * 512 * QKV_STRIDE];
__device__ __nv_bfloat16 g_v_split[Bb * Hh * 512 * QKV_STRIDE];
__device__ __nv_bfloat16 g_enc_split[Bb * 512 * 256];
__device__ __nv_bfloat16 g_att_split[Bb * 512 * 256];
__device__ __nv_bfloat16 g_mh_split[Bb * 512 * 256];

__device__ __forceinline__ unsigned smem_u32(const void* p) {
    unsigned a;
    asm("{ .reg .u64 t; cvta.to.shared.u64 t, %1; cvt.u32.u64 %0, t; }"
        : "=r"(a) : "l"(p));
    return a;
}

__device__ __forceinline__ void ldmx4(unsigned* r, unsigned addr) {
    asm volatile(
        "ldmatrix.sync.aligned.m8n8.x4.shared.b16 {%0,%1,%2,%3}, [%4];"
        : "=r"(r[0]), "=r"(r[1]), "=r"(r[2]), "=r"(r[3]) : "r"(addr));
}
__device__ __forceinline__ void ldmx4t(unsigned* r, unsigned addr) {
    asm volatile(
        "ldmatrix.sync.aligned.m8n8.x4.trans.shared.b16 {%0,%1,%2,%3}, [%4];"
        : "=r"(r[0]), "=r"(r[1]), "=r"(r[2]), "=r"(r[3]) : "r"(addr));
}
__device__ __forceinline__ void mma16816(float* c, const unsigned* a,
                                         unsigned b0, unsigned b1) {
    asm volatile(
        "mma.sync.aligned.m16n8k16.row.col.f32.bf16.bf16.f32 "
        "{%0,%1,%2,%3}, {%4,%5,%6,%7}, {%8,%9}, {%0,%1,%2,%3};"
        : "+f"(c[0]), "+f"(c[1]), "+f"(c[2]), "+f"(c[3])
        : "r"(a[0]), "r"(a[1]), "r"(a[2]), "r"(a[3]), "r"(b0), "r"(b1));
}
__device__ __forceinline__ unsigned pack_bf2(float x, float y) {
    __nv_bfloat162 h = __floats2bfloat162_rn(x, y);
    return *(unsigned*)&h;
}

// split one float4 into hi/lo bf16x2 pairs and store at smem row layout
__device__ __forceinline__ void split_store(__nv_bfloat16* d, float4 v) {
    __nv_bfloat162 h01 = __floats2bfloat162_rn(v.x, v.y);
    __nv_bfloat162 h23 = __floats2bfloat162_rn(v.z, v.w);
    float2 f01 = __bfloat1622float2(h01);
    float2 f23 = __bfloat1622float2(h23);
    __nv_bfloat162 l01 = __floats2bfloat162_rn(v.x - f01.x, v.y - f01.y);
    __nv_bfloat162 l23 = __floats2bfloat162_rn(v.z - f23.x, v.w - f23.y);
    *(__nv_bfloat162*)(d) = h01;
    *(__nv_bfloat162*)(d + 2) = h23;
    *(__nv_bfloat162*)(d + 128) = l01;
    *(__nv_bfloat162*)(d + 130) = l23;
}

// ---------------------------------------------------------------------------
// HMMA 64x64 projection core (v12/v13, occ 3)
// ---------------------------------------------------------------------------
#define PRJ64_SMEM ((64 + 64) * 264 * 2)

template <bool A_FP32>
__device__ __forceinline__ void proj64_body(
    const void* __restrict__ A0v, const float* __restrict__ W0,
    const void* __restrict__ A1v, const float* __restrict__ W1,
    const float* __restrict__ bias, __nv_bfloat16* __restrict__ outb,
    float scale, int mode, int m0, int f0) {
    extern __shared__ char smem[];
    __nv_bfloat16* As = (__nv_bfloat16*)smem;   // [64][264]
    __nv_bfloat16* Ws = As + 64 * 264;          // [64][264]

    const int t = threadIdx.x;
    const int w = t >> 5, lane = t & 31;
    const int wrow = (w & 3) * 16;
    const int whalf = w >> 2;

    float acc[4][4];
    #pragma unroll
    for (int i = 0; i < 4; ++i)
        acc[i][0] = acc[i][1] = acc[i][2] = acc[i][3] = 0.f;

    const int npass = (A1v != nullptr) ? 2 : 1;
    for (int p = 0; p < npass; ++p) {
        const void* Ap = p ? A1v : A0v;
        const float* Wp = p ? W1 : W0;
        if (p) __syncthreads();
        #pragma unroll
        for (int k = 0; k < 8; ++k) {
            int i4 = t + 256 * k;
            int row = i4 >> 5, e4 = i4 & 31;
            if (A_FP32) {
                float4 v = ((const float4*)Ap)[(size_t)(m0 + row) * 32 + e4];
                split_store(As + row * 264 + e4 * 4, v);
            } else {
                int m = m0 + row;
                int bb = m / Nn, nn = m - bb * Nn;
                uint4 v = *((const uint4*)((const __nv_bfloat16*)Ap +
                            ((size_t)(bb * 512 + nn)) * 256) + e4);
                *(uint4*)(As + row * 264 + e4 * 8) = v;
            }
        }
        #pragma unroll
        for (int k = 0; k < 8; ++k) {
            int i4 = t + 256 * k;
            int row = i4 >> 5, e4 = i4 & 31;
            float4 v = ((const float4*)Wp)[(size_t)(f0 + row) * 32 + e4];
            split_store(Ws + row * 264 + e4 * 4, v);
        }
        __syncthreads();

        unsigned arowb = wrow + (lane & 15);
        unsigned acolb = (lane >> 4) * 8;
        unsigned browb = whalf * 32 + (lane & 15);
        #pragma unroll
        for (int kk = 0; kk < 8; ++kk) {
            unsigned aaddr = smem_u32(As + arowb * 264 + acolb + kk * 16);
            unsigned ah[4], al[4];
            ldmx4(ah, aaddr);
            ldmx4(al, aaddr + 128 * 2);
            #pragma unroll
            for (int np = 0; np < 2; ++np) {
                unsigned baddr = smem_u32(Ws + (np * 16 + browb) * 264 +
                                          acolb + kk * 16);
                unsigned bh[4], bl[4];
                ldmx4(bh, baddr);
                ldmx4(bl, baddr + 128 * 2);
                mma16816(acc[2 * np],     ah, bh[0], bh[2]);
                mma16816(acc[2 * np + 1], ah, bh[1], bh[3]);
                mma16816(acc[2 * np],     ah, bl[0], bl[2]);
                mma16816(acc[2 * np + 1], ah, bl[1], bl[3]);
                mma16816(acc[2 * np],     al, bh[0], bh[2]);
                mma16816(acc[2 * np + 1], al, bh[1], bh[3]);
            }
        }
        if (p + 1 < npass) __syncthreads();
    }

    const int mr0 = m0 + wrow + (lane >> 2);
    const int mr1 = mr0 + 8;
    const int b0 = mr0 / Nn, n0v = mr0 - b0 * Nn;
    const int b1 = mr1 / Nn, n1v = mr1 - b1 * Nn;
    #pragma unroll
    for (int ntile = 0; ntile < 4; ++ntile) {
        int f = f0 + whalf * 32 + ntile * 8 + (lane & 3) * 2;
        float bb0 = 0.f, bb1 = 0.f;
        if (bias) { bb0 = bias[f]; bb1 = bias[f + 1]; }
        float r00 = (acc[ntile][0] + bb0) * scale;
        float r01 = (acc[ntile][1] + bb1) * scale;
        float r10 = (acc[ntile][2] + bb0) * scale;
        float r11 = (acc[ntile][3] + bb1) * scale;
        __nv_bfloat162 h0 = __floats2bfloat162_rn(r00, r01);
        float2 ff0 = __bfloat1622float2(h0);
        unsigned lo0 = pack_bf2(r00 - ff0.x, r01 - ff0.y);
        __nv_bfloat162 h1 = __floats2bfloat162_rn(r10, r11);
        float2 ff1 = __bfloat1622float2(h1);
        unsigned lo1 = pack_bf2(r10 - ff1.x, r11 - ff1.y);
        if (mode == 0) {
            int h = f >> 4, d = f & 15;
            size_t base0 =
                ((size_t)((b0 * Hh + h) * 512 + n0v)) * QKV_STRIDE + d;
            *(unsigned*)(outb + base0) = *(unsigned*)&h0;
            *(unsigned*)(outb + base0 + 16) = lo0;
            size_t base1 =
                ((size_t)((b1 * Hh + h) * 512 + n1v)) * QKV_STRIDE + d;
            *(unsigned*)(outb + base1) = *(unsigned*)&h1;
            *(unsigned*)(outb + base1 + 16) = lo1;
        } else {
            size_t base0 = ((size_t)(b0 * 512 + n0v)) * 256 + f;
            *(unsigned*)(outb + base0) = *(unsigned*)&h0;
            *(unsigned*)(outb + base0 + 128) = lo0;
            size_t base1 = ((size_t)(b1 * 512 + n1v)) * 256 + f;
            *(unsigned*)(outb + base1) = *(unsigned*)&h1;
            *(unsigned*)(outb + base1 + 128) = lo1;
        }
    }
}

// ---------------------------------------------------------------------------
// Launch 1: qkv projections (inline fp32 splits) + enc split + maskbits.
// ---------------------------------------------------------------------------
__global__ void __launch_bounds__(256, 3)
qkv_prep_kernel(const float* __restrict__ enc_nodes,
                const float* __restrict__ enc_first,
                const float* __restrict__ enc_last,
                const float* __restrict__ mask,
                const float* __restrict__ Wqf, const float* __restrict__ Wql,
                const float* __restrict__ Wk, const float* __restrict__ Wv) {
    int bi = blockIdx.x;
    if (bi < 3000) {
        const float QS = 1.4426950408889634f * 0.25f;  // log2e / sqrt(D)
        int which = bi / 1000;
        int rem = bi - which * 1000;
        int m0 = (rem >> 1) * 64;
        int f0 = (rem & 1) * 64;
        if (which == 0)
            proj64_body<true>(enc_first, Wqf, enc_last, Wql, nullptr,
                              g_q_split, QS, 0, m0, f0);
        else if (which == 1)
            proj64_body<true>(enc_nodes, Wk, nullptr, nullptr, nullptr,
                              g_k_split, 1.0f, 0, m0, f0);
        else
            proj64_body<true>(enc_nodes, Wv, nullptr, nullptr, nullptr,
                              g_v_split, 1.0f, 0, m0, f0);
    } else if (bi < 3064) {
        int b = bi - 3000;
        int t = threadIdx.x;
        const float4* src = (const float4*)(enc_nodes + (size_t)b * Nn * 128);
        for (int i4 = t; i4 < Nn * 32; i4 += 256) {
            int n = i4 >> 5, e4 = i4 & 31;
            split_store(g_enc_split + ((size_t)(b * 512 + n)) * 256 + e4 * 4,
                        src[i4]);
        }
    } else {
        int t = threadIdx.x;
        int wid = t >> 5, lane = t & 31;
        int rowbase = (bi - 3064) * 128 + wid * 16;
        for (int rr = 0; rr < 16; ++rr) {
            int row = rowbase + rr;
            const float* mrow = mask + (size_t)row * Nn;
            unsigned* brow = g_maskbits + (size_t)row * 16;
            #pragma unroll
            for (int w = 0; w < 16; ++w) {
                int g = w * 32 + lane;
                float v = (g < Nn) ? mrow[g] : -1e9f;
                unsigned bal = __ballot_sync(0xffffffffu, v > -1.0f);
                if (lane == 0) brow[w] = bal;
            }
        }
    }
}

// ---------------------------------------------------------------------------
// Launch 3: combine (A = att_split bf16, W = Wc fp32 inline split)
// ---------------------------------------------------------------------------
__global__ void __launch_bounds__(256, 3)
combine_mma_kernel(const float* __restrict__ Wc, const float* __restrict__ bc) {
    int bi = blockIdx.x;
    proj64_body<false>(g_att_split, Wc, nullptr, nullptr, bc,
                       g_mh_split, 1.0f, 1, (bi >> 1) * 64, (bi & 1) * 64);
}

// ---------------------------------------------------------------------------
// Launch 2: attention via HMMA (v12/v13/v14, best measured)
// ---------------------------------------------------------------------------
#define ATT_SMEM ((128 + 512 + 512) * QKV_STRIDE * 2)

__global__ void __launch_bounds__(256, 2)
attn_mma_kernel() {
    extern __shared__ char smem[];
    __nv_bfloat16* Qs = (__nv_bfloat16*)smem;
    __nv_bfloat16* Ks = Qs + 128 * QKV_STRIDE;
    __nv_bfloat16* Vs = Ks + 512 * QKV_STRIDE;

    const int t = threadIdx.x;
    const int w = t >> 5, lane = t & 31;
    const int bi = blockIdx.x;
    const int bh = bi >> 2, qt = bi & 3;
    const int b = bh >> 3, h = bh & 7;
    const int q0 = qt * 128;

    {
        const uint4* qsrc =
            (const uint4*)(g_q_split + ((size_t)bh * 512 + q0) * QKV_STRIDE);
        #pragma unroll
        for (int k = 0; k < 3; ++k) {
            int i = t + 256 * k;
            if (i < 640) ((uint4*)Qs)[i] = qsrc[i];
        }
        const uint4* ksrc =
            (const uint4*)(g_k_split + (size_t)bh * 512 * QKV_STRIDE);
        #pragma unroll
        for (int k = 0; k < 10; ++k)
            ((uint4*)Ks)[t + 256 * k] = ksrc[t + 256 * k];
        const uint4* vsrc =
            (const uint4*)(g_v_split + (size_t)bh * 512 * QKV_STRIDE);
        #pragma unroll
        for (int k = 0; k < 10; ++k)
            ((uint4*)Vs)[t + 256 * k] = vsrc[t + 256 * k];
    }
    __syncthreads();

    unsigned aq_hi[4], aq_lo[4];
    {
        unsigned qaddr = smem_u32(Qs + (w * 16 + (lane & 15)) * QKV_STRIDE +
                                  (lane >> 4) * 8);
        ldmx4(aq_hi, qaddr);
        ldmx4(aq_lo, qaddr + 32);
    }

    float oacc[2][4];
    #pragma unroll
    for (int j = 0; j < 4; ++j) { oacc[0][j] = 0.f; oacc[1][j] = 0.f; }
    float rs0 = 0.f, rs1 = 0.f;

    const int nr0 = q0 + w * 16 + (lane >> 2);
    const int nr1 = nr0 + 8;
    const int nr0c = (nr0 < Nn) ? nr0 : 0;
    const int nr1c = (nr1 < Nn) ? nr1 : 0;

    for (int gt = 0; gt < 4; ++gt) {
        const int g0 = gt * 128;

        float sacc[16][4];
        #pragma unroll
        for (int i = 0; i < 16; ++i)
            sacc[i][0] = sacc[i][1] = sacc[i][2] = sacc[i][3] = 0.f;

        #pragma unroll
        for (int np = 0; np < 8; ++np) {
            unsigned ka = smem_u32(Ks + (g0 + np * 16 + (lane & 15)) *
                                            QKV_STRIDE +
                                   (lane >> 4) * 8);
            unsigned kh[4], kl[4];
            ldmx4(kh, ka);
            ldmx4(kl, ka + 32);
            mma16816(sacc[2 * np],     aq_hi, kh[0], kh[2]);
            mma16816(sacc[2 * np],     aq_hi, kl[0], kl[2]);
            mma16816(sacc[2 * np],     aq_lo, kh[0], kh[2]);
            mma16816(sacc[2 * np + 1], aq_hi, kh[1], kh[3]);
            mma16816(sacc[2 * np + 1], aq_hi, kl[1], kl[3]);
            mma16816(sacc[2 * np + 1], aq_lo, kh[1], kh[3]);
        }

        uint4 m0 = *(const uint4*)(g_maskbits + ((size_t)b * Nn + nr0c) * 16 +
                                   gt * 4);
        uint4 m1 = *(const uint4*)(g_maskbits + ((size_t)b * Nn + nr1c) * 16 +
                                   gt * 4);
        unsigned mw0[4] = {m0.x, m0.y, m0.z, m0.w};
        unsigned mw1[4] = {m1.x, m1.y, m1.z, m1.w};

        #pragma unroll
        for (int kk = 0; kk < 8; ++kk) {
            unsigned pf_hi[4], pf_lo[4];
            #pragma unroll
            for (int half = 0; half < 2; ++half) {
                int ntile = 2 * kk + half;
                unsigned w0 = mw0[ntile >> 2];
                unsigned w1 = mw1[ntile >> 2];
                int bitb = (ntile & 3) * 8 + (lane & 3) * 2;
                float p00 = exp2f(sacc[ntile][0]);
                float p01 = exp2f(sacc[ntile][1]);
                float p10 = exp2f(sacc[ntile][2]);
                float p11 = exp2f(sacc[ntile][3]);
                p00 = ((w0 >> bitb) & 1u) ? p00 : 0.f;
                p01 = ((w0 >> (bitb + 1)) & 1u) ? p01 : 0.f;
                p10 = ((w1 >> bitb) & 1u) ? p10 : 0.f;
                p11 = ((w1 >> (bitb + 1)) & 1u) ? p11 : 0.f;
                rs0 += p00 + p01;
                rs1 += p10 + p11;
                __nv_bfloat162 h0 = __floats2bfloat162_rn(p00, p01);
                __nv_bfloat162 h1 = __floats2bfloat162_rn(p10, p11);
                float2 hf0 = __bfloat1622float2(h0);
                float2 hf1 = __bfloat1622float2(h1);
                pf_hi[2 * half + 0] = *(unsigned*)&h0;
                pf_hi[2 * half + 1] = *(unsigned*)&h1;
                pf_lo[2 * half + 0] = pack_bf2(p00 - hf0.x, p01 - hf0.y);
                pf_lo[2 * half + 1] = pack_bf2(p10 - hf1.x, p11 - hf1.y);
            }
            unsigned va = smem_u32(Vs + (g0 + kk * 16 + (lane & 15)) *
                                            QKV_STRIDE +
                                   (lane >> 4) * 8);
            unsigned vh[4], vl[4];
            ldmx4t(vh, va);
            ldmx4t(vl, va + 32);
            mma16816(oacc[0], pf_hi, vh[0], vh[1]);
            mma16816(oacc[0], pf_hi, vl[0], vl[1]);
            mma16816(oacc[0], pf_lo, vh[0], vh[1]);
            mma16816(oacc[1], pf_hi, vh[2], vh[3]);
            mma16816(oacc[1], pf_hi, vl[2], vl[3]);
            mma16816(oacc[1], pf_lo, vh[2], vh[3]);
        }
    }

    rs0 += __shfl_xor_sync(0xffffffffu, rs0, 1);
    rs0 += __shfl_xor_sync(0xffffffffu, rs0, 2);
    rs1 += __shfl_xor_sync(0xffffffffu, rs1, 1);
    rs1 += __shfl_xor_sync(0xffffffffu, rs1, 2);
    float inv0 = __fdividef(1.0f, rs0);
    float inv1 = __fdividef(1.0f, rs1);

    const int d0 = (lane & 3) * 2;
    if (nr0 < Nn) {
        size_t base = ((size_t)(b * 512 + nr0)) * 256 + h * 16 + d0;
        float v0 = oacc[0][0] * inv0, v1 = oacc[0][1] * inv0;
        __nv_bfloat162 hh = __floats2bfloat162_rn(v0, v1);
        float2 hf = __bfloat1622float2(hh);
        *(unsigned*)(g_att_split + base) = *(unsigned*)&hh;
        *(unsigned*)(g_att_split + base + 128) =
            pack_bf2(v0 - hf.x, v1 - hf.y);
        v0 = oacc[1][0] * inv0; v1 = oacc[1][1] * inv0;
        hh = __floats2bfloat162_rn(v0, v1);
        hf = __bfloat1622float2(hh);
        *(unsigned*)(g_att_split + base + 8) = *(unsigned*)&hh;
        *(unsigned*)(g_att_split + base + 8 + 128) =
            pack_bf2(v0 - hf.x, v1 - hf.y);
    }
    if (nr1 < Nn) {
        size_t base = ((size_t)(b * 512 + nr1)) * 256 + h * 16 + d0;
        float v0 = oacc[0][2] * inv1, v1 = oacc[0][3] * inv1;
        __nv_bfloat162 hh = __floats2bfloat162_rn(v0, v1);
        float2 hf = __bfloat1622float2(hh);
        *(unsigned*)(g_att_split + base) = *(unsigned*)&hh;
        *(unsigned*)(g_att_split + base + 128) =
            pack_bf2(v0 - hf.x, v1 - hf.y);
        v0 = oacc[1][2] * inv1; v1 = oacc[1][3] * inv1;
        hh = __floats2bfloat162_rn(v0, v1);
        hf = __bfloat1622float2(hh);
        *(unsigned*)(g_att_split + base + 8) = *(unsigned*)&hh;
        *(unsigned*)(g_att_split + base + 8 + 128) =
            pack_bf2(v0 - hf.x, v1 - hf.y);
    }
}

// ---------------------------------------------------------------------------
// Launch 4: pointer v15 — 128-row blocks, occ 2, single wave (256 blocks),
// warp = 16 rows x 64 g: 8 independent acc chains, LDSM:MMA = 0.42,
// 8 gt iterations of 64 g, register-pipelined B tiles.
// smem: As 128x264 + Bs 64x264 + rsum[128] = 101888 B.
// ---------------------------------------------------------------------------
#define AS_STRIDE 264
#define PTR_SMEM ((128 + 64) * AS_STRIDE * 2 + 512)

__global__ void __launch_bounds__(256, 2)
pointer_mma_kernel(float* __restrict__ out) {
    extern __shared__ char smem[];
    __nv_bfloat16* As = (__nv_bfloat16*)smem;                 // [128][264]
    __nv_bfloat16* Bs = As + 128 * AS_STRIDE;                 // [64][264]
    float* rsum = (float*)(Bs + 64 * AS_STRIDE);              // [128]

    const int t = threadIdx.x;
    const int w = t >> 5, lane = t & 31;
    const int b = blockIdx.x >> 2;
    const int nt = blockIdx.x & 3;
    const int n0 = nt * 128;
    const int wrow = w * 16;          // each warp owns a unique 16-row stripe

    // As fill: 128 rows of mh_split (rows >=500 are zero padding)
    {
        const uint4* src =
            (const uint4*)(g_mh_split + ((size_t)(b * 512 + n0)) * 256);
        #pragma unroll
        for (int k = 0; k < 16; ++k) {
            int i4 = t + 256 * k;
            int row = i4 >> 5, c8 = i4 & 31;
            *(uint4*)(As + row * AS_STRIDE + c8 * 8) = src[i4];
        }
    }

    const float C1 = 0.08838834764831845f * 2.0f * 1.4426950408889634f;
    const float C2 = 10.0f * 1.4426950408889634f;

    const int nr0 = n0 + wrow + (lane >> 2);
    const int nr1 = nr0 + 8;
    const int nr0c = (nr0 < Nn) ? nr0 : 0;
    const int nr1c = (nr1 < Nn) ? nr1 : 0;
    float rs0 = 0.f, rs1 = 0.f;

    const unsigned arowb = wrow + (lane & 15);
    const unsigned kcolb = (lane >> 4) * 8;

    // prefetch gt=0 B tile (64 rows x 32 uint4 = 2048 / 256 threads = 8 each)
    uint4 pf[8];
    {
        const uint4* src = (const uint4*)(g_enc_split +
                                          ((size_t)(b * 512)) * 256);
        #pragma unroll
        for (int k = 0; k < 8; ++k) pf[k] = src[t + 256 * k];
    }

    for (int gt = 0; gt < 8; ++gt) {
        // store prefetched tile
        #pragma unroll
        for (int k = 0; k < 8; ++k) {
            int i4 = t + 256 * k;
            int row = i4 >> 5, c8 = i4 & 31;
            *(uint4*)(Bs + row * AS_STRIDE + c8 * 8) = pf[k];
        }
        __syncthreads();
        // issue next tile's loads (overlap with MMA below)
        if (gt < 7) {
            const uint4* src = (const uint4*)(g_enc_split +
                ((size_t)(b * 512 + (gt + 1) * 64)) * 256);
            #pragma unroll
            for (int k = 0; k < 8; ++k) pf[k] = src[t + 256 * k];
        }

        float acc[8][4];
        #pragma unroll
        for (int i = 0; i < 8; ++i)
            acc[i][0] = acc[i][1] = acc[i][2] = acc[i][3] = 0.f;

        #pragma unroll
        for (int kk = 0; kk < 8; ++kk) {
            unsigned aaddr = smem_u32(As + arowb * AS_STRIDE + kcolb +
                                      kk * 16);
            unsigned ah[4], al[4];
            ldmx4(ah, aaddr);
            ldmx4(al, aaddr + 128 * 2);
            #pragma unroll
            for (int n16 = 0; n16 < 4; ++n16) {
                unsigned baddr = smem_u32(Bs + (n16 * 16 + (lane & 15)) *
                                              AS_STRIDE + kcolb + kk * 16);
                unsigned bh[4], bl[4];
                ldmx4(bh, baddr);
                ldmx4(bl, baddr + 128 * 2);
                mma16816(acc[2 * n16],     ah, bh[0], bh[2]);
                mma16816(acc[2 * n16 + 1], ah, bh[1], bh[3]);
                mma16816(acc[2 * n16],     ah, bl[0], bl[2]);
                mma16816(acc[2 * n16 + 1], ah, bl[1], bl[3]);
                mma16816(acc[2 * n16],     al, bh[0], bh[2]);
                mma16816(acc[2 * n16 + 1], al, bh[1], bh[3]);
            }
        }

        const int g0 = gt * 64;
        const int mw = gt * 2;
        unsigned w00 = g_maskbits[((size_t)b * Nn + nr0c) * 16 + mw];
        unsigned w01 = g_maskbits[((size_t)b * Nn + nr0c) * 16 + mw + 1];
        unsigned w10 = g_maskbits[((size_t)b * Nn + nr1c) * 16 + mw];
        unsigned w11 = g_maskbits[((size_t)b * Nn + nr1c) * 16 + mw + 1];

        #pragma unroll
        for (int j = 0; j < 8; ++j) {
            unsigned w0 = (j < 4) ? w00 : w01;
            unsigned w1 = (j < 4) ? w10 : w11;
            int bitb = (j & 3) * 8 + (lane & 3) * 2;
            float p00, p01, p10, p11;
            {
                float u = exp2f(acc[j][0] * C1);
                p00 = exp2f(C2 * (1.0f - __fdividef(2.0f, u + 1.0f)));
            }
            {
                float u = exp2f(acc[j][1] * C1);
                p01 = exp2f(C2 * (1.0f - __fdividef(2.0f, u + 1.0f)));
            }
            {
                float u = exp2f(acc[j][2] * C1);
                p10 = exp2f(C2 * (1.0f - __fdividef(2.0f, u + 1.0f)));
            }
            {
                float u = exp2f(acc[j][3] * C1);
                p11 = exp2f(C2 * (1.0f - __fdividef(2.0f, u + 1.0f)));
            }
            p00 = ((w0 >> bitb) & 1u) ? p00 : 0.f;
            p01 = ((w0 >> (bitb + 1)) & 1u) ? p01 : 0.f;
            p10 = ((w1 >> bitb) & 1u) ? p10 : 0.f;
            p11 = ((w1 >> (bitb + 1)) & 1u) ? p11 : 0.f;
            rs0 += p00 + p01;
            rs1 += p10 + p11;
            int g = g0 + j * 8 + (lane & 3) * 2;
            if (g < Nn) {
                if (nr0 < Nn)
                    *(float2*)(out + ((size_t)b * Nn + nr0) * Nn + g) =
                        make_float2(p00, p01);
                if (nr1 < Nn)
                    *(float2*)(out + ((size_t)b * Nn + nr1) * Nn + g) =
                        make_float2(p10, p11);
            }
        }
        __syncthreads();   // Bs consumed; next STS may overwrite
    }

    // per-warp rowsums (each warp owns its rows across all g)
    rs0 += __shfl_xor_sync(0xffffffffu, rs0, 1);
    rs0 += __shfl_xor_sync(0xffffffffu, rs0, 2);
    rs1 += __shfl_xor_sync(0xffffffffu, rs1, 1);
    rs1 += __shfl_xor_sync(0xffffffffu, rs1, 2);
    if ((lane & 3) == 0) {
        rsum[wrow + (lane >> 2)] = rs0;
        rsum[wrow + (lane >> 2) + 8] = rs1;
    }
    __syncthreads();

    // rescale: 128 rows x 125 float4
    for (int i4 = t; i4 < 128 * 125; i4 += 256) {
        int row = i4 / 125, c4 = i4 - row * 125;
        int n = n0 + row;
        if (n < Nn) {
            float inv = __fdividef(1.0f, rsum[row]);
            float4* po = (float4*)(out + ((size_t)b * Nn + n) * Nn) + c4;
            float4 p = *po;
            p.x *= inv; p.y *= inv; p.z *= inv; p.w *= inv;
            *po = p;
        }
    }
}

// ---------------------------------------------------------------------------
// Launch
// ---------------------------------------------------------------------------
extern "C" void kernel_launch(void* const* d_in, const int* in_sizes, int n_in,
                              void* d_out, int out_size) {
    const float* enc_nodes = (const float*)d_in[0];
    const float* enc_first = (const float*)d_in[1];
    const float* enc_last  = (const float*)d_in[2];
    const float* mask      = (const float*)d_in[3];
    const float* Wq_first  = (const float*)d_in[4];
    const float* Wq_last   = (const float*)d_in[5];
    const float* Wk        = (const float*)d_in[6];
    const float* Wv        = (const float*)d_in[7];
    const float* Wc        = (const float*)d_in[8];
    const float* bc        = (const float*)d_in[9];
    float* out = (float*)d_out;

    static int configured = 0;
    if (!configured) {
        cudaFuncSetAttribute(qkv_prep_kernel,
            cudaFuncAttributeMaxDynamicSharedMemorySize, PRJ64_SMEM);
        cudaFuncSetAttribute(combine_mma_kernel,
            cudaFuncAttributeMaxDynamicSharedMemorySize, PRJ64_SMEM);
        cudaFuncSetAttribute(attn_mma_kernel,
            cudaFuncAttributeMaxDynamicSharedMemorySize, ATT_SMEM);
        cudaFuncSetAttribute(pointer_mma_kernel,
            cudaFuncAttributeMaxDynamicSharedMemorySize, PTR_SMEM);
        configured = 1;
    }

    // 1) qkv (inline fp32 splits) + enc split + maskbits
    qkv_prep_kernel<<<3314, 256, PRJ64_SMEM>>>(enc_nodes, enc_first, enc_last,
                                               mask, Wq_first, Wq_last,
                                               Wk, Wv);
    // 2) attention
    attn_mma_kernel<<<Bb * Hh * 4, 256, ATT_SMEM>>>();
    // 3) combine
    combine_mma_kernel<<<1000, 256, PRJ64_SMEM>>>(Wc, bc);
    // 4) pointer (256 blocks @ occ 2, single wave, 8 chains/warp)
    pointer_mma_kernel<<<Bb * 4, 256, PTR_SMEM>>>(out);

    (void)in_sizes; (void)n_in; (void)out_size;
}

// round 16
// speedup vs baseline: 1.0309x; 1.0309x over previous
#include <cuda_runtime.h>
#include <cuda_bf16.h>
#include <math.h>

// ---------------------------------------------------------------------------
// POMO decoder v16 — v14 base (best: 291.4us); cp.async for pointer/attn
// tile loads (double-buffered pointer B). B=64, N=500, E=128, H=8, D=16
// ---------------------------------------------------------------------------

#define Bb 64
#define Nn 500
#define Hh 8
#define QKV_STRIDE 40

typedef unsigned long long ull;

__device__ unsigned g_maskbits[Bb * Nn * 16];
__device__ __nv_bfloat16 g_q_split[Bb * Hh * 512 * QKV_STRIDE];
__device__ __nv_bfloat16 g_k_split[Bb * Hh * 512 * QKV_STRIDE];
__device__ __nv_bfloat16 g_v_split[Bb * Hh * 512 * QKV_STRIDE];
__device__ __nv_bfloat16 g_enc_split[Bb * 512 * 256];
__device__ __nv_bfloat16 g_att_split[Bb * 512 * 256];
__device__ __nv_bfloat16 g_mh_split[Bb * 512 * 256];

__device__ __forceinline__ unsigned smem_u32(const void* p) {
    unsigned a;
    asm("{ .reg .u64 t; cvta.to.shared.u64 t, %1; cvt.u32.u64 %0, t; }"
        : "=r"(a) : "l"(p));
    return a;
}

#define CP_ASYNC16(dst, src)                                                   \
    asm volatile("cp.async.cg.shared.global [%0], [%1], 16;"                   \
                 :: "r"(dst), "l"(src))
#define CP_COMMIT() asm volatile("cp.async.commit_group;" ::: "memory")
#define CP_WAIT0()  asm volatile("cp.async.wait_group 0;" ::: "memory")

__device__ __forceinline__ void ldmx4(unsigned* r, unsigned addr) {
    asm volatile(
        "ldmatrix.sync.aligned.m8n8.x4.shared.b16 {%0,%1,%2,%3}, [%4];"
        : "=r"(r[0]), "=r"(r[1]), "=r"(r[2]), "=r"(r[3]) : "r"(addr));
}
__device__ __forceinline__ void ldmx4t(unsigned* r, unsigned addr) {
    asm volatile(
        "ldmatrix.sync.aligned.m8n8.x4.trans.shared.b16 {%0,%1,%2,%3}, [%4];"
        : "=r"(r[0]), "=r"(r[1]), "=r"(r[2]), "=r"(r[3]) : "r"(addr));
}
__device__ __forceinline__ void mma16816(float* c, const unsigned* a,
                                         unsigned b0, unsigned b1) {
    asm volatile(
        "mma.sync.aligned.m16n8k16.row.col.f32.bf16.bf16.f32 "
        "{%0,%1,%2,%3}, {%4,%5,%6,%7}, {%8,%9}, {%0,%1,%2,%3};"
        : "+f"(c[0]), "+f"(c[1]), "+f"(c[2]), "+f"(c[3])
        : "r"(a[0]), "r"(a[1]), "r"(a[2]), "r"(a[3]), "r"(b0), "r"(b1));
}
__device__ __forceinline__ unsigned pack_bf2(float x, float y) {
    __nv_bfloat162 h = __floats2bfloat162_rn(x, y);
    return *(unsigned*)&h;
}

// split one float4 into hi/lo bf16x2 pairs and store at smem row layout
__device__ __forceinline__ void split_store(__nv_bfloat16* d, float4 v) {
    __nv_bfloat162 h01 = __floats2bfloat162_rn(v.x, v.y);
    __nv_bfloat162 h23 = __floats2bfloat162_rn(v.z, v.w);
    float2 f01 = __bfloat1622float2(h01);
    float2 f23 = __bfloat1622float2(h23);
    __nv_bfloat162 l01 = __floats2bfloat162_rn(v.x - f01.x, v.y - f01.y);
    __nv_bfloat162 l23 = __floats2bfloat162_rn(v.z - f23.x, v.w - f23.y);
    *(__nv_bfloat162*)(d) = h01;
    *(__nv_bfloat162*)(d + 2) = h23;
    *(__nv_bfloat162*)(d + 128) = l01;
    *(__nv_bfloat162*)(d + 130) = l23;
}

// ---------------------------------------------------------------------------
// HMMA 64x64 projection core (v12/v13, occ 3 — conversions need registers,
// so no cp.async here)
// ---------------------------------------------------------------------------
#define PRJ64_SMEM ((64 + 64) * 264 * 2)

template <bool A_FP32>
__device__ __forceinline__ void proj64_body(
    const void* __restrict__ A0v, const float* __restrict__ W0,
    const void* __restrict__ A1v, const float* __restrict__ W1,
    const float* __restrict__ bias, __nv_bfloat16* __restrict__ outb,
    float scale, int mode, int m0, int f0) {
    extern __shared__ char smem[];
    __nv_bfloat16* As = (__nv_bfloat16*)smem;   // [64][264]
    __nv_bfloat16* Ws = As + 64 * 264;          // [64][264]

    const int t = threadIdx.x;
    const int w = t >> 5, lane = t & 31;
    const int wrow = (w & 3) * 16;
    const int whalf = w >> 2;

    float acc[4][4];
    #pragma unroll
    for (int i = 0; i < 4; ++i)
        acc[i][0] = acc[i][1] = acc[i][2] = acc[i][3] = 0.f;

    const int npass = (A1v != nullptr) ? 2 : 1;
    for (int p = 0; p < npass; ++p) {
        const void* Ap = p ? A1v : A0v;
        const float* Wp = p ? W1 : W0;
        if (p) __syncthreads();
        #pragma unroll
        for (int k = 0; k < 8; ++k) {
            int i4 = t + 256 * k;
            int row = i4 >> 5, e4 = i4 & 31;
            if (A_FP32) {
                float4 v = ((const float4*)Ap)[(size_t)(m0 + row) * 32 + e4];
                split_store(As + row * 264 + e4 * 4, v);
            } else {
                int m = m0 + row;
                int bb = m / Nn, nn = m - bb * Nn;
                uint4 v = *((const uint4*)((const __nv_bfloat16*)Ap +
                            ((size_t)(bb * 512 + nn)) * 256) + e4);
                *(uint4*)(As + row * 264 + e4 * 8) = v;
            }
        }
        #pragma unroll
        for (int k = 0; k < 8; ++k) {
            int i4 = t + 256 * k;
            int row = i4 >> 5, e4 = i4 & 31;
            float4 v = ((const float4*)Wp)[(size_t)(f0 + row) * 32 + e4];
            split_store(Ws + row * 264 + e4 * 4, v);
        }
        __syncthreads();

        unsigned arowb = wrow + (lane & 15);
        unsigned acolb = (lane >> 4) * 8;
        unsigned browb = whalf * 32 + (lane & 15);
        #pragma unroll
        for (int kk = 0; kk < 8; ++kk) {
            unsigned aaddr = smem_u32(As + arowb * 264 + acolb + kk * 16);
            unsigned ah[4], al[4];
            ldmx4(ah, aaddr);
            ldmx4(al, aaddr + 128 * 2);
            #pragma unroll
            for (int np = 0; np < 2; ++np) {
                unsigned baddr = smem_u32(Ws + (np * 16 + browb) * 264 +
                                          acolb + kk * 16);
                unsigned bh[4], bl[4];
                ldmx4(bh, baddr);
                ldmx4(bl, baddr + 128 * 2);
                mma16816(acc[2 * np],     ah, bh[0], bh[2]);
                mma16816(acc[2 * np + 1], ah, bh[1], bh[3]);
                mma16816(acc[2 * np],     ah, bl[0], bl[2]);
                mma16816(acc[2 * np + 1], ah, bl[1], bl[3]);
                mma16816(acc[2 * np],     al, bh[0], bh[2]);
                mma16816(acc[2 * np + 1], al, bh[1], bh[3]);
            }
        }
        if (p + 1 < npass) __syncthreads();
    }

    const int mr0 = m0 + wrow + (lane >> 2);
    const int mr1 = mr0 + 8;
    const int b0 = mr0 / Nn, n0v = mr0 - b0 * Nn;
    const int b1 = mr1 / Nn, n1v = mr1 - b1 * Nn;
    #pragma unroll
    for (int ntile = 0; ntile < 4; ++ntile) {
        int f = f0 + whalf * 32 + ntile * 8 + (lane & 3) * 2;
        float bb0 = 0.f, bb1 = 0.f;
        if (bias) { bb0 = bias[f]; bb1 = bias[f + 1]; }
        float r00 = (acc[ntile][0] + bb0) * scale;
        float r01 = (acc[ntile][1] + bb1) * scale;
        float r10 = (acc[ntile][2] + bb0) * scale;
        float r11 = (acc[ntile][3] + bb1) * scale;
        __nv_bfloat162 h0 = __floats2bfloat162_rn(r00, r01);
        float2 ff0 = __bfloat1622float2(h0);
        unsigned lo0 = pack_bf2(r00 - ff0.x, r01 - ff0.y);
        __nv_bfloat162 h1 = __floats2bfloat162_rn(r10, r11);
        float2 ff1 = __bfloat1622float2(h1);
        unsigned lo1 = pack_bf2(r10 - ff1.x, r11 - ff1.y);
        if (mode == 0) {
            int h = f >> 4, d = f & 15;
            size_t base0 =
                ((size_t)((b0 * Hh + h) * 512 + n0v)) * QKV_STRIDE + d;
            *(unsigned*)(outb + base0) = *(unsigned*)&h0;
            *(unsigned*)(outb + base0 + 16) = lo0;
            size_t base1 =
                ((size_t)((b1 * Hh + h) * 512 + n1v)) * QKV_STRIDE + d;
            *(unsigned*)(outb + base1) = *(unsigned*)&h1;
            *(unsigned*)(outb + base1 + 16) = lo1;
        } else {
            size_t base0 = ((size_t)(b0 * 512 + n0v)) * 256 + f;
            *(unsigned*)(outb + base0) = *(unsigned*)&h0;
            *(unsigned*)(outb + base0 + 128) = lo0;
            size_t base1 = ((size_t)(b1 * 512 + n1v)) * 256 + f;
            *(unsigned*)(outb + base1) = *(unsigned*)&h1;
            *(unsigned*)(outb + base1 + 128) = lo1;
        }
    }
}

// ---------------------------------------------------------------------------
// Launch 1: qkv projections (inline fp32 splits) + enc split + maskbits.
// ---------------------------------------------------------------------------
__global__ void __launch_bounds__(256, 3)
qkv_prep_kernel(const float* __restrict__ enc_nodes,
                const float* __restrict__ enc_first,
                const float* __restrict__ enc_last,
                const float* __restrict__ mask,
                const float* __restrict__ Wqf, const float* __restrict__ Wql,
                const float* __restrict__ Wk, const float* __restrict__ Wv) {
    int bi = blockIdx.x;
    if (bi < 3000) {
        const float QS = 1.4426950408889634f * 0.25f;  // log2e / sqrt(D)
        int which = bi / 1000;
        int rem = bi - which * 1000;
        int m0 = (rem >> 1) * 64;
        int f0 = (rem & 1) * 64;
        if (which == 0)
            proj64_body<true>(enc_first, Wqf, enc_last, Wql, nullptr,
                              g_q_split, QS, 0, m0, f0);
        else if (which == 1)
            proj64_body<true>(enc_nodes, Wk, nullptr, nullptr, nullptr,
                              g_k_split, 1.0f, 0, m0, f0);
        else
            proj64_body<true>(enc_nodes, Wv, nullptr, nullptr, nullptr,
                              g_v_split, 1.0f, 0, m0, f0);
    } else if (bi < 3064) {
        int b = bi - 3000;
        int t = threadIdx.x;
        const float4* src = (const float4*)(enc_nodes + (size_t)b * Nn * 128);
        for (int i4 = t; i4 < Nn * 32; i4 += 256) {
            int n = i4 >> 5, e4 = i4 & 31;
            split_store(g_enc_split + ((size_t)(b * 512 + n)) * 256 + e4 * 4,
                        src[i4]);
        }
    } else {
        int t = threadIdx.x;
        int wid = t >> 5, lane = t & 31;
        int rowbase = (bi - 3064) * 128 + wid * 16;
        for (int rr = 0; rr < 16; ++rr) {
            int row = rowbase + rr;
            const float* mrow = mask + (size_t)row * Nn;
            unsigned* brow = g_maskbits + (size_t)row * 16;
            #pragma unroll
            for (int w = 0; w < 16; ++w) {
                int g = w * 32 + lane;
                float v = (g < Nn) ? mrow[g] : -1e9f;
                unsigned bal = __ballot_sync(0xffffffffu, v > -1.0f);
                if (lane == 0) brow[w] = bal;
            }
        }
    }
}

// ---------------------------------------------------------------------------
// Launch 3: combine (A = att_split bf16, W = Wc fp32 inline split)
// ---------------------------------------------------------------------------
__global__ void __launch_bounds__(256, 3)
combine_mma_kernel(const float* __restrict__ Wc, const float* __restrict__ bc) {
    int bi = blockIdx.x;
    proj64_body<false>(g_att_split, Wc, nullptr, nullptr, bc,
                       g_mh_split, 1.0f, 1, (bi >> 1) * 64, (bi & 1) * 64);
}

// ---------------------------------------------------------------------------
// Launch 2: attention via HMMA (v14 core; prologue via cp.async)
// ---------------------------------------------------------------------------
#define ATT_SMEM ((128 + 512 + 512) * QKV_STRIDE * 2)

__global__ void __launch_bounds__(256, 2)
attn_mma_kernel() {
    extern __shared__ char smem[];
    __nv_bfloat16* Qs = (__nv_bfloat16*)smem;
    __nv_bfloat16* Ks = Qs + 128 * QKV_STRIDE;
    __nv_bfloat16* Vs = Ks + 512 * QKV_STRIDE;

    const int t = threadIdx.x;
    const int w = t >> 5, lane = t & 31;
    const int bi = blockIdx.x;
    const int bh = bi >> 2, qt = bi & 3;
    const int b = bh >> 3, h = bh & 7;
    const int q0 = qt * 128;

    {
        const uint4* qsrc =
            (const uint4*)(g_q_split + ((size_t)bh * 512 + q0) * QKV_STRIDE);
        #pragma unroll
        for (int k = 0; k < 3; ++k) {
            int i = t + 256 * k;
            if (i < 640)
                CP_ASYNC16(smem_u32((uint4*)Qs + i), qsrc + i);
        }
        const uint4* ksrc =
            (const uint4*)(g_k_split + (size_t)bh * 512 * QKV_STRIDE);
        const uint4* vsrc =
            (const uint4*)(g_v_split + (size_t)bh * 512 * QKV_STRIDE);
        #pragma unroll
        for (int k = 0; k < 10; ++k) {
            int i = t + 256 * k;
            CP_ASYNC16(smem_u32((uint4*)Ks + i), ksrc + i);
            CP_ASYNC16(smem_u32((uint4*)Vs + i), vsrc + i);
        }
        CP_COMMIT();
        CP_WAIT0();
    }
    __syncthreads();

    unsigned aq_hi[4], aq_lo[4];
    {
        unsigned qaddr = smem_u32(Qs + (w * 16 + (lane & 15)) * QKV_STRIDE +
                                  (lane >> 4) * 8);
        ldmx4(aq_hi, qaddr);
        ldmx4(aq_lo, qaddr + 32);
    }

    float oacc[2][4];
    #pragma unroll
    for (int j = 0; j < 4; ++j) { oacc[0][j] = 0.f; oacc[1][j] = 0.f; }
    float rs0 = 0.f, rs1 = 0.f;

    const int nr0 = q0 + w * 16 + (lane >> 2);
    const int nr1 = nr0 + 8;
    const int nr0c = (nr0 < Nn) ? nr0 : 0;
    const int nr1c = (nr1 < Nn) ? nr1 : 0;

    for (int gt = 0; gt < 4; ++gt) {
        const int g0 = gt * 128;

        float sacc[16][4];
        #pragma unroll
        for (int i = 0; i < 16; ++i)
            sacc[i][0] = sacc[i][1] = sacc[i][2] = sacc[i][3] = 0.f;

        #pragma unroll
        for (int np = 0; np < 8; ++np) {
            unsigned ka = smem_u32(Ks + (g0 + np * 16 + (lane & 15)) *
                                            QKV_STRIDE +
                                   (lane >> 4) * 8);
            unsigned kh[4], kl[4];
            ldmx4(kh, ka);
            ldmx4(kl, ka + 32);
            mma16816(sacc[2 * np],     aq_hi, kh[0], kh[2]);
            mma16816(sacc[2 * np],     aq_hi, kl[0], kl[2]);
            mma16816(sacc[2 * np],     aq_lo, kh[0], kh[2]);
            mma16816(sacc[2 * np + 1], aq_hi, kh[1], kh[3]);
            mma16816(sacc[2 * np + 1], aq_hi, kl[1], kl[3]);
            mma16816(sacc[2 * np + 1], aq_lo, kh[1], kh[3]);
        }

        uint4 m0 = *(const uint4*)(g_maskbits + ((size_t)b * Nn + nr0c) * 16 +
                                   gt * 4);
        uint4 m1 = *(const uint4*)(g_maskbits + ((size_t)b * Nn + nr1c) * 16 +
                                   gt * 4);
        unsigned mw0[4] = {m0.x, m0.y, m0.z, m0.w};
        unsigned mw1[4] = {m1.x, m1.y, m1.z, m1.w};

        #pragma unroll
        for (int kk = 0; kk < 8; ++kk) {
            unsigned pf_hi[4], pf_lo[4];
            #pragma unroll
            for (int half = 0; half < 2; ++half) {
                int ntile = 2 * kk + half;
                unsigned w0 = mw0[ntile >> 2];
                unsigned w1 = mw1[ntile >> 2];
                int bitb = (ntile & 3) * 8 + (lane & 3) * 2;
                float p00 = exp2f(sacc[ntile][0]);
                float p01 = exp2f(sacc[ntile][1]);
                float p10 = exp2f(sacc[ntile][2]);
                float p11 = exp2f(sacc[ntile][3]);
                p00 = ((w0 >> bitb) & 1u) ? p00 : 0.f;
                p01 = ((w0 >> (bitb + 1)) & 1u) ? p01 : 0.f;
                p10 = ((w1 >> bitb) & 1u) ? p10 : 0.f;
                p11 = ((w1 >> (bitb + 1)) & 1u) ? p11 : 0.f;
                rs0 += p00 + p01;
                rs1 += p10 + p11;
                __nv_bfloat162 h0 = __floats2bfloat162_rn(p00, p01);
                __nv_bfloat162 h1 = __floats2bfloat162_rn(p10, p11);
                float2 hf0 = __bfloat1622float2(h0);
                float2 hf1 = __bfloat1622float2(h1);
                pf_hi[2 * half + 0] = *(unsigned*)&h0;
                pf_hi[2 * half + 1] = *(unsigned*)&h1;
                pf_lo[2 * half + 0] = pack_bf2(p00 - hf0.x, p01 - hf0.y);
                pf_lo[2 * half + 1] = pack_bf2(p10 - hf1.x, p11 - hf1.y);
            }
            unsigned va = smem_u32(Vs + (g0 + kk * 16 + (lane & 15)) *
                                            QKV_STRIDE +
                                   (lane >> 4) * 8);
            unsigned vh[4], vl[4];
            ldmx4t(vh, va);
            ldmx4t(vl, va + 32);
            mma16816(oacc[0], pf_hi, vh[0], vh[1]);
            mma16816(oacc[0], pf_hi, vl[0], vl[1]);
            mma16816(oacc[0], pf_lo, vh[0], vh[1]);
            mma16816(oacc[1], pf_hi, vh[2], vh[3]);
            mma16816(oacc[1], pf_hi, vl[2], vl[3]);
            mma16816(oacc[1], pf_lo, vh[2], vh[3]);
        }
    }

    rs0 += __shfl_xor_sync(0xffffffffu, rs0, 1);
    rs0 += __shfl_xor_sync(0xffffffffu, rs0, 2);
    rs1 += __shfl_xor_sync(0xffffffffu, rs1, 1);
    rs1 += __shfl_xor_sync(0xffffffffu, rs1, 2);
    float inv0 = __fdividef(1.0f, rs0);
    float inv1 = __fdividef(1.0f, rs1);

    const int d0 = (lane & 3) * 2;
    if (nr0 < Nn) {
        size_t base = ((size_t)(b * 512 + nr0)) * 256 + h * 16 + d0;
        float v0 = oacc[0][0] * inv0, v1 = oacc[0][1] * inv0;
        __nv_bfloat162 hh = __floats2bfloat162_rn(v0, v1);
        float2 hf = __bfloat1622float2(hh);
        *(unsigned*)(g_att_split + base) = *(unsigned*)&hh;
        *(unsigned*)(g_att_split + base + 128) =
            pack_bf2(v0 - hf.x, v1 - hf.y);
        v0 = oacc[1][0] * inv0; v1 = oacc[1][1] * inv0;
        hh = __floats2bfloat162_rn(v0, v1);
        hf = __bfloat1622float2(hh);
        *(unsigned*)(g_att_split + base + 8) = *(unsigned*)&hh;
        *(unsigned*)(g_att_split + base + 8 + 128) =
            pack_bf2(v0 - hf.x, v1 - hf.y);
    }
    if (nr1 < Nn) {
        size_t base = ((size_t)(b * 512 + nr1)) * 256 + h * 16 + d0;
        float v0 = oacc[0][2] * inv1, v1 = oacc[0][3] * inv1;
        __nv_bfloat162 hh = __floats2bfloat162_rn(v0, v1);
        float2 hf = __bfloat1622float2(hh);
        *(unsigned*)(g_att_split + base) = *(unsigned*)&hh;
        *(unsigned*)(g_att_split + base + 128) =
            pack_bf2(v0 - hf.x, v1 - hf.y);
        v0 = oacc[1][2] * inv1; v1 = oacc[1][3] * inv1;
        hh = __floats2bfloat162_rn(v0, v1);
        hf = __bfloat1622float2(hh);
        *(unsigned*)(g_att_split + base + 8) = *(unsigned*)&hh;
        *(unsigned*)(g_att_split + base + 8 + 128) =
            pack_bf2(v0 - hf.x, v1 - hf.y);
    }
}

// ---------------------------------------------------------------------------
// Launch 4: pointer v16 — v14 shape (128-row blocks, 16x32 warp tile, occ 2,
// 256-block single wave) with cp.async As fill + double-buffered Bs.
// smem: As 128x264 + Bs 2x32x264 + rsum[128] = 101888 B.
// ---------------------------------------------------------------------------
#define AS_STRIDE 264
#define PTR_SMEM ((128 + 64) * AS_STRIDE * 2 + 512)

__global__ void __launch_bounds__(256, 2)
pointer_mma_kernel(float* __restrict__ out) {
    extern __shared__ char smem[];
    __nv_bfloat16* As = (__nv_bfloat16*)smem;                 // [128][264]
    __nv_bfloat16* Bs0 = As + 128 * AS_STRIDE;                // [32][264]
    __nv_bfloat16* Bs1 = Bs0 + 32 * AS_STRIDE;                // [32][264]
    float* rsum = (float*)(Bs1 + 32 * AS_STRIDE);             // [128]

    const int t = threadIdx.x;
    const int w = t >> 5, lane = t & 31;
    const int b = blockIdx.x >> 2;
    const int nt = blockIdx.x & 3;
    const int n0 = nt * 128;
    const int wrow = w * 16;          // each warp owns a unique 16-row stripe

    // As fill + Bs buf0 fill via cp.async
    {
        const uint4* src =
            (const uint4*)(g_mh_split + ((size_t)(b * 512 + n0)) * 256);
        #pragma unroll
        for (int k = 0; k < 16; ++k) {
            int i4 = t + 256 * k;
            int row = i4 >> 5, c8 = i4 & 31;
            CP_ASYNC16(smem_u32(As + row * AS_STRIDE + c8 * 8), src + i4);
        }
        const uint4* bsrc =
            (const uint4*)(g_enc_split + ((size_t)(b * 512)) * 256);
        #pragma unroll
        for (int k = 0; k < 4; ++k) {
            int i4 = t + 256 * k;
            int row = i4 >> 5, c8 = i4 & 31;
            CP_ASYNC16(smem_u32(Bs0 + row * AS_STRIDE + c8 * 8), bsrc + i4);
        }
        CP_COMMIT();
        CP_WAIT0();
    }
    __syncthreads();

    const float C1 = 0.08838834764831845f * 2.0f * 1.4426950408889634f;
    const float C2 = 10.0f * 1.4426950408889634f;

    const int nr0 = n0 + wrow + (lane >> 2);
    const int nr1 = nr0 + 8;
    const int nr0c = (nr0 < Nn) ? nr0 : 0;
    const int nr1c = (nr1 < Nn) ? nr1 : 0;
    float rs0 = 0.f, rs1 = 0.f;

    const unsigned arowb = wrow + (lane & 15);
    const unsigned kcolb = (lane >> 4) * 8;

    for (int gt = 0; gt < 16; ++gt) {
        __nv_bfloat16* Bc = (gt & 1) ? Bs1 : Bs0;
        __nv_bfloat16* Bn = (gt & 1) ? Bs0 : Bs1;
        // issue next tile's cp.async into the other buffer
        if (gt < 15) {
            const uint4* src = (const uint4*)(g_enc_split +
                ((size_t)(b * 512 + (gt + 1) * 32)) * 256);
            #pragma unroll
            for (int k = 0; k < 4; ++k) {
                int i4 = t + 256 * k;
                int row = i4 >> 5, c8 = i4 & 31;
                CP_ASYNC16(smem_u32(Bn + row * AS_STRIDE + c8 * 8), src + i4);
            }
            CP_COMMIT();
        }

        float acc[4][4];
        #pragma unroll
        for (int i = 0; i < 4; ++i)
            acc[i][0] = acc[i][1] = acc[i][2] = acc[i][3] = 0.f;

        #pragma unroll
        for (int kk = 0; kk < 8; ++kk) {
            unsigned aaddr = smem_u32(As + arowb * AS_STRIDE + kcolb +
                                      kk * 16);
            unsigned ah[4], al[4];
            ldmx4(ah, aaddr);
            ldmx4(al, aaddr + 128 * 2);
            #pragma unroll
            for (int n16 = 0; n16 < 2; ++n16) {
                unsigned baddr = smem_u32(Bc + (n16 * 16 + (lane & 15)) *
                                              AS_STRIDE + kcolb + kk * 16);
                unsigned bh[4], bl[4];
                ldmx4(bh, baddr);
                ldmx4(bl, baddr + 128 * 2);
                mma16816(acc[2 * n16],     ah, bh[0], bh[2]);
                mma16816(acc[2 * n16 + 1], ah, bh[1], bh[3]);
                mma16816(acc[2 * n16],     ah, bl[0], bl[2]);
                mma16816(acc[2 * n16 + 1], ah, bl[1], bl[3]);
                mma16816(acc[2 * n16],     al, bh[0], bh[2]);
                mma16816(acc[2 * n16 + 1], al, bh[1], bh[3]);
            }
        }

        const int g0 = gt * 32;
        unsigned w0 = g_maskbits[((size_t)b * Nn + nr0c) * 16 + gt];
        unsigned w1 = g_maskbits[((size_t)b * Nn + nr1c) * 16 + gt];

        #pragma unroll
        for (int j = 0; j < 4; ++j) {
            int bitb = j * 8 + (lane & 3) * 2;
            float p00, p01, p10, p11;
            {
                float u = exp2f(acc[j][0] * C1);
                p00 = exp2f(C2 * (1.0f - __fdividef(2.0f, u + 1.0f)));
            }
            {
                float u = exp2f(acc[j][1] * C1);
                p01 = exp2f(C2 * (1.0f - __fdividef(2.0f, u + 1.0f)));
            }
            {
                float u = exp2f(acc[j][2] * C1);
                p10 = exp2f(C2 * (1.0f - __fdividef(2.0f, u + 1.0f)));
            }
            {
                float u = exp2f(acc[j][3] * C1);
                p11 = exp2f(C2 * (1.0f - __fdividef(2.0f, u + 1.0f)));
            }
            p00 = ((w0 >> bitb) & 1u) ? p00 : 0.f;
            p01 = ((w0 >> (bitb + 1)) & 1u) ? p01 : 0.f;
            p10 = ((w1 >> bitb) & 1u) ? p10 : 0.f;
            p11 = ((w1 >> (bitb + 1)) & 1u) ? p11 : 0.f;
            rs0 += p00 + p01;
            rs1 += p10 + p11;
            int g = g0 + j * 8 + (lane & 3) * 2;
            if (g < Nn) {
                if (nr0 < Nn)
                    *(float2*)(out + ((size_t)b * Nn + nr0) * Nn + g) =
                        make_float2(p00, p01);
                if (nr1 < Nn)
                    *(float2*)(out + ((size_t)b * Nn + nr1) * Nn + g) =
                        make_float2(p10, p11);
            }
        }
        if (gt < 15) CP_WAIT0();
        __syncthreads();
    }

    // per-warp rowsums (each warp owns its rows across all g)
    rs0 += __shfl_xor_sync(0xffffffffu, rs0, 1);
    rs0 += __shfl_xor_sync(0xffffffffu, rs0, 2);
    rs1 += __shfl_xor_sync(0xffffffffu, rs1, 1);
    rs1 += __shfl_xor_sync(0xffffffffu, rs1, 2);
    if ((lane & 3) == 0) {
        rsum[wrow + (lane >> 2)] = rs0;
        rsum[wrow + (lane >> 2) + 8] = rs1;
    }
    __syncthreads();

    // rescale: 128 rows x 125 float4 (L2-hot RMW)
    for (int i4 = t; i4 < 128 * 125; i4 += 256) {
        int row = i4 / 125, c4 = i4 - row * 125;
        int n = n0 + row;
        if (n < Nn) {
            float inv = __fdividef(1.0f, rsum[row]);
            float4* po = (float4*)(out + ((size_t)b * Nn + n) * Nn) + c4;
            float4 p = *po;
            p.x *= inv; p.y *= inv; p.z *= inv; p.w *= inv;
            *po = p;
        }
    }
}

// ---------------------------------------------------------------------------
// Launch
// ---------------------------------------------------------------------------
extern "C" void kernel_launch(void* const* d_in, const int* in_sizes, int n_in,
                              void* d_out, int out_size) {
    const float* enc_nodes = (const float*)d_in[0];
    const float* enc_first = (const float*)d_in[1];
    const float* enc_last  = (const float*)d_in[2];
    const float* mask      = (const float*)d_in[3];
    const float* Wq_first  = (const float*)d_in[4];
    const float* Wq_last   = (const float*)d_in[5];
    const float* Wk        = (const float*)d_in[6];
    const float* Wv        = (const float*)d_in[7];
    const float* Wc        = (const float*)d_in[8];
    const float* bc        = (const float*)d_in[9];
    float* out = (float*)d_out;

    static int configured = 0;
    if (!configured) {
        cudaFuncSetAttribute(qkv_prep_kernel,
            cudaFuncAttributeMaxDynamicSharedMemorySize, PRJ64_SMEM);
        cudaFuncSetAttribute(combine_mma_kernel,
            cudaFuncAttributeMaxDynamicSharedMemorySize, PRJ64_SMEM);
        cudaFuncSetAttribute(attn_mma_kernel,
            cudaFuncAttributeMaxDynamicSharedMemorySize, ATT_SMEM);
        cudaFuncSetAttribute(pointer_mma_kernel,
            cudaFuncAttributeMaxDynamicSharedMemorySize, PTR_SMEM);
        configured = 1;
    }

    // 1) qkv (inline fp32 splits) + enc split + maskbits
    qkv_prep_kernel<<<3314, 256, PRJ64_SMEM>>>(enc_nodes, enc_first, enc_last,
                                               mask, Wq_first, Wq_last,
                                               Wk, Wv);
    // 2) attention
    attn_mma_kernel<<<Bb * Hh * 4, 256, ATT_SMEM>>>();
    // 3) combine
    combine_mma_kernel<<<1000, 256, PRJ64_SMEM>>>(Wc, bc);
    // 4) pointer (v14 shape + cp.async double buffer)
    pointer_mma_kernel<<<Bb * 4, 256, PTR_SMEM>>>(out);

    (void)in_sizes; (void)n_in; (void)out_size;
}

// round 17
// speedup vs baseline: 1.0641x; 1.0322x over previous
#include <cuda_runtime.h>
#include <cuda_bf16.h>
#include <math.h>

// ---------------------------------------------------------------------------
// POMO decoder v17 — v16 base (best: 284.8us); combine fused into pointer
// prologue (mh computed in-block from att_split + Wc). 3 launches total.
// B=64, N=500, E=128, H=8, D=16
// ---------------------------------------------------------------------------

#define Bb 64
#define Nn 500
#define Hh 8
#define QKV_STRIDE 40

typedef unsigned long long ull;

__device__ unsigned g_maskbits[Bb * Nn * 16];
__device__ __nv_bfloat16 g_q_split[Bb * Hh * 512 * QKV_STRIDE];
__device__ __nv_bfloat16 g_k_split[Bb * Hh * 512 * QKV_STRIDE];
__device__ __nv_bfloat16 g_v_split[Bb * Hh * 512 * QKV_STRIDE];
__device__ __nv_bfloat16 g_enc_split[Bb * 512 * 256];
__device__ __nv_bfloat16 g_att_split[Bb * 512 * 256];

__device__ __forceinline__ unsigned smem_u32(const void* p) {
    unsigned a;
    asm("{ .reg .u64 t; cvta.to.shared.u64 t, %1; cvt.u32.u64 %0, t; }"
        : "=r"(a) : "l"(p));
    return a;
}

#define CP_ASYNC16(dst, src)                                                   \
    asm volatile("cp.async.cg.shared.global [%0], [%1], 16;"                   \
                 :: "r"(dst), "l"(src))
#define CP_COMMIT() asm volatile("cp.async.commit_group;" ::: "memory")
#define CP_WAIT0()  asm volatile("cp.async.wait_group 0;" ::: "memory")

__device__ __forceinline__ void ldmx4(unsigned* r, unsigned addr) {
    asm volatile(
        "ldmatrix.sync.aligned.m8n8.x4.shared.b16 {%0,%1,%2,%3}, [%4];"
        : "=r"(r[0]), "=r"(r[1]), "=r"(r[2]), "=r"(r[3]) : "r"(addr));
}
__device__ __forceinline__ void ldmx4t(unsigned* r, unsigned addr) {
    asm volatile(
        "ldmatrix.sync.aligned.m8n8.x4.trans.shared.b16 {%0,%1,%2,%3}, [%4];"
        : "=r"(r[0]), "=r"(r[1]), "=r"(r[2]), "=r"(r[3]) : "r"(addr));
}
__device__ __forceinline__ void mma16816(float* c, const unsigned* a,
                                         unsigned b0, unsigned b1) {
    asm volatile(
        "mma.sync.aligned.m16n8k16.row.col.f32.bf16.bf16.f32 "
        "{%0,%1,%2,%3}, {%4,%5,%6,%7}, {%8,%9}, {%0,%1,%2,%3};"
        : "+f"(c[0]), "+f"(c[1]), "+f"(c[2]), "+f"(c[3])
        : "r"(a[0]), "r"(a[1]), "r"(a[2]), "r"(a[3]), "r"(b0), "r"(b1));
}
__device__ __forceinline__ unsigned pack_bf2(float x, float y) {
    __nv_bfloat162 h = __floats2bfloat162_rn(x, y);
    return *(unsigned*)&h;
}

// split one float4 into hi/lo bf16x2 pairs and store at smem row layout
__device__ __forceinline__ void split_store(__nv_bfloat16* d, float4 v) {
    __nv_bfloat162 h01 = __floats2bfloat162_rn(v.x, v.y);
    __nv_bfloat162 h23 = __floats2bfloat162_rn(v.z, v.w);
    float2 f01 = __bfloat1622float2(h01);
    float2 f23 = __bfloat1622float2(h23);
    __nv_bfloat162 l01 = __floats2bfloat162_rn(v.x - f01.x, v.y - f01.y);
    __nv_bfloat162 l23 = __floats2bfloat162_rn(v.z - f23.x, v.w - f23.y);
    *(__nv_bfloat162*)(d) = h01;
    *(__nv_bfloat162*)(d + 2) = h23;
    *(__nv_bfloat162*)(d + 128) = l01;
    *(__nv_bfloat162*)(d + 130) = l23;
}

// ---------------------------------------------------------------------------
// HMMA 64x64 projection core (qkv only now; occ 3)
// ---------------------------------------------------------------------------
#define PRJ64_SMEM ((64 + 64) * 264 * 2)

__device__ __forceinline__ void proj64_body(
    const float* __restrict__ A0, const float* __restrict__ W0,
    const float* __restrict__ A1, const float* __restrict__ W1,
    __nv_bfloat16* __restrict__ outb, float scale, int m0, int f0) {
    extern __shared__ char smem[];
    __nv_bfloat16* As = (__nv_bfloat16*)smem;   // [64][264]
    __nv_bfloat16* Ws = As + 64 * 264;          // [64][264]

    const int t = threadIdx.x;
    const int w = t >> 5, lane = t & 31;
    const int wrow = (w & 3) * 16;
    const int whalf = w >> 2;

    float acc[4][4];
    #pragma unroll
    for (int i = 0; i < 4; ++i)
        acc[i][0] = acc[i][1] = acc[i][2] = acc[i][3] = 0.f;

    const int npass = (A1 != nullptr) ? 2 : 1;
    for (int p = 0; p < npass; ++p) {
        const float* Ap = p ? A1 : A0;
        const float* Wp = p ? W1 : W0;
        if (p) __syncthreads();
        #pragma unroll
        for (int k = 0; k < 8; ++k) {
            int i4 = t + 256 * k;
            int row = i4 >> 5, e4 = i4 & 31;
            float4 v = ((const float4*)Ap)[(size_t)(m0 + row) * 32 + e4];
            split_store(As + row * 264 + e4 * 4, v);
        }
        #pragma unroll
        for (int k = 0; k < 8; ++k) {
            int i4 = t + 256 * k;
            int row = i4 >> 5, e4 = i4 & 31;
            float4 v = ((const float4*)Wp)[(size_t)(f0 + row) * 32 + e4];
            split_store(Ws + row * 264 + e4 * 4, v);
        }
        __syncthreads();

        unsigned arowb = wrow + (lane & 15);
        unsigned acolb = (lane >> 4) * 8;
        unsigned browb = whalf * 32 + (lane & 15);
        #pragma unroll
        for (int kk = 0; kk < 8; ++kk) {
            unsigned aaddr = smem_u32(As + arowb * 264 + acolb + kk * 16);
            unsigned ah[4], al[4];
            ldmx4(ah, aaddr);
            ldmx4(al, aaddr + 128 * 2);
            #pragma unroll
            for (int np = 0; np < 2; ++np) {
                unsigned baddr = smem_u32(Ws + (np * 16 + browb) * 264 +
                                          acolb + kk * 16);
                unsigned bh[4], bl[4];
                ldmx4(bh, baddr);
                ldmx4(bl, baddr + 128 * 2);
                mma16816(acc[2 * np],     ah, bh[0], bh[2]);
                mma16816(acc[2 * np + 1], ah, bh[1], bh[3]);
                mma16816(acc[2 * np],     ah, bl[0], bl[2]);
                mma16816(acc[2 * np + 1], ah, bl[1], bl[3]);
                mma16816(acc[2 * np],     al, bh[0], bh[2]);
                mma16816(acc[2 * np + 1], al, bh[1], bh[3]);
            }
        }
        if (p + 1 < npass) __syncthreads();
    }

    const int mr0 = m0 + wrow + (lane >> 2);
    const int mr1 = mr0 + 8;
    const int b0 = mr0 / Nn, n0v = mr0 - b0 * Nn;
    const int b1 = mr1 / Nn, n1v = mr1 - b1 * Nn;
    #pragma unroll
    for (int ntile = 0; ntile < 4; ++ntile) {
        int f = f0 + whalf * 32 + ntile * 8 + (lane & 3) * 2;
        float r00 = acc[ntile][0] * scale;
        float r01 = acc[ntile][1] * scale;
        float r10 = acc[ntile][2] * scale;
        float r11 = acc[ntile][3] * scale;
        __nv_bfloat162 h0 = __floats2bfloat162_rn(r00, r01);
        float2 ff0 = __bfloat1622float2(h0);
        unsigned lo0 = pack_bf2(r00 - ff0.x, r01 - ff0.y);
        __nv_bfloat162 h1 = __floats2bfloat162_rn(r10, r11);
        float2 ff1 = __bfloat1622float2(h1);
        unsigned lo1 = pack_bf2(r10 - ff1.x, r11 - ff1.y);
        int h = f >> 4, d = f & 15;
        size_t base0 = ((size_t)((b0 * Hh + h) * 512 + n0v)) * QKV_STRIDE + d;
        *(unsigned*)(outb + base0) = *(unsigned*)&h0;
        *(unsigned*)(outb + base0 + 16) = lo0;
        size_t base1 = ((size_t)((b1 * Hh + h) * 512 + n1v)) * QKV_STRIDE + d;
        *(unsigned*)(outb + base1) = *(unsigned*)&h1;
        *(unsigned*)(outb + base1 + 16) = lo1;
    }
}

// ---------------------------------------------------------------------------
// Launch 1: qkv projections (inline fp32 splits) + enc split + maskbits.
// ---------------------------------------------------------------------------
__global__ void __launch_bounds__(256, 3)
qkv_prep_kernel(const float* __restrict__ enc_nodes,
                const float* __restrict__ enc_first,
                const float* __restrict__ enc_last,
                const float* __restrict__ mask,
                const float* __restrict__ Wqf, const float* __restrict__ Wql,
                const float* __restrict__ Wk, const float* __restrict__ Wv) {
    int bi = blockIdx.x;
    if (bi < 3000) {
        const float QS = 1.4426950408889634f * 0.25f;  // log2e / sqrt(D)
        int which = bi / 1000;
        int rem = bi - which * 1000;
        int m0 = (rem >> 1) * 64;
        int f0 = (rem & 1) * 64;
        if (which == 0)
            proj64_body(enc_first, Wqf, enc_last, Wql, g_q_split, QS, m0, f0);
        else if (which == 1)
            proj64_body(enc_nodes, Wk, nullptr, nullptr, g_k_split, 1.0f,
                        m0, f0);
        else
            proj64_body(enc_nodes, Wv, nullptr, nullptr, g_v_split, 1.0f,
                        m0, f0);
    } else if (bi < 3064) {
        int b = bi - 3000;
        int t = threadIdx.x;
        const float4* src = (const float4*)(enc_nodes + (size_t)b * Nn * 128);
        for (int i4 = t; i4 < Nn * 32; i4 += 256) {
            int n = i4 >> 5, e4 = i4 & 31;
            split_store(g_enc_split + ((size_t)(b * 512 + n)) * 256 + e4 * 4,
                        src[i4]);
        }
    } else {
        int t = threadIdx.x;
        int wid = t >> 5, lane = t & 31;
        int rowbase = (bi - 3064) * 128 + wid * 16;
        for (int rr = 0; rr < 16; ++rr) {
            int row = rowbase + rr;
            const float* mrow = mask + (size_t)row * Nn;
            unsigned* brow = g_maskbits + (size_t)row * 16;
            #pragma unroll
            for (int w = 0; w < 16; ++w) {
                int g = w * 32 + lane;
                float v = (g < Nn) ? mrow[g] : -1e9f;
                unsigned bal = __ballot_sync(0xffffffffu, v > -1.0f);
                if (lane == 0) brow[w] = bal;
            }
        }
    }
}

// ---------------------------------------------------------------------------
// Launch 2: attention via HMMA (v16, best measured)
// ---------------------------------------------------------------------------
#define ATT_SMEM ((128 + 512 + 512) * QKV_STRIDE * 2)

__global__ void __launch_bounds__(256, 2)
attn_mma_kernel() {
    extern __shared__ char smem[];
    __nv_bfloat16* Qs = (__nv_bfloat16*)smem;
    __nv_bfloat16* Ks = Qs + 128 * QKV_STRIDE;
    __nv_bfloat16* Vs = Ks + 512 * QKV_STRIDE;

    const int t = threadIdx.x;
    const int w = t >> 5, lane = t & 31;
    const int bi = blockIdx.x;
    const int bh = bi >> 2, qt = bi & 3;
    const int b = bh >> 3, h = bh & 7;
    const int q0 = qt * 128;

    {
        const uint4* qsrc =
            (const uint4*)(g_q_split + ((size_t)bh * 512 + q0) * QKV_STRIDE);
        #pragma unroll
        for (int k = 0; k < 3; ++k) {
            int i = t + 256 * k;
            if (i < 640)
                CP_ASYNC16(smem_u32((uint4*)Qs + i), qsrc + i);
        }
        const uint4* ksrc =
            (const uint4*)(g_k_split + (size_t)bh * 512 * QKV_STRIDE);
        const uint4* vsrc =
            (const uint4*)(g_v_split + (size_t)bh * 512 * QKV_STRIDE);
        #pragma unroll
        for (int k = 0; k < 10; ++k) {
            int i = t + 256 * k;
            CP_ASYNC16(smem_u32((uint4*)Ks + i), ksrc + i);
            CP_ASYNC16(smem_u32((uint4*)Vs + i), vsrc + i);
        }
        CP_COMMIT();
        CP_WAIT0();
    }
    __syncthreads();

    unsigned aq_hi[4], aq_lo[4];
    {
        unsigned qaddr = smem_u32(Qs + (w * 16 + (lane & 15)) * QKV_STRIDE +
                                  (lane >> 4) * 8);
        ldmx4(aq_hi, qaddr);
        ldmx4(aq_lo, qaddr + 32);
    }

    float oacc[2][4];
    #pragma unroll
    for (int j = 0; j < 4; ++j) { oacc[0][j] = 0.f; oacc[1][j] = 0.f; }
    float rs0 = 0.f, rs1 = 0.f;

    const int nr0 = q0 + w * 16 + (lane >> 2);
    const int nr1 = nr0 + 8;
    const int nr0c = (nr0 < Nn) ? nr0 : 0;
    const int nr1c = (nr1 < Nn) ? nr1 : 0;

    for (int gt = 0; gt < 4; ++gt) {
        const int g0 = gt * 128;

        float sacc[16][4];
        #pragma unroll
        for (int i = 0; i < 16; ++i)
            sacc[i][0] = sacc[i][1] = sacc[i][2] = sacc[i][3] = 0.f;

        #pragma unroll
        for (int np = 0; np < 8; ++np) {
            unsigned ka = smem_u32(Ks + (g0 + np * 16 + (lane & 15)) *
                                            QKV_STRIDE +
                                   (lane >> 4) * 8);
            unsigned kh[4], kl[4];
            ldmx4(kh, ka);
            ldmx4(kl, ka + 32);
            mma16816(sacc[2 * np],     aq_hi, kh[0], kh[2]);
            mma16816(sacc[2 * np],     aq_hi, kl[0], kl[2]);
            mma16816(sacc[2 * np],     aq_lo, kh[0], kh[2]);
            mma16816(sacc[2 * np + 1], aq_hi, kh[1], kh[3]);
            mma16816(sacc[2 * np + 1], aq_hi, kl[1], kl[3]);
            mma16816(sacc[2 * np + 1], aq_lo, kh[1], kh[3]);
        }

        uint4 m0 = *(const uint4*)(g_maskbits + ((size_t)b * Nn + nr0c) * 16 +
                                   gt * 4);
        uint4 m1 = *(const uint4*)(g_maskbits + ((size_t)b * Nn + nr1c) * 16 +
                                   gt * 4);
        unsigned mw0[4] = {m0.x, m0.y, m0.z, m0.w};
        unsigned mw1[4] = {m1.x, m1.y, m1.z, m1.w};

        #pragma unroll
        for (int kk = 0; kk < 8; ++kk) {
            unsigned pf_hi[4], pf_lo[4];
            #pragma unroll
            for (int half = 0; half < 2; ++half) {
                int ntile = 2 * kk + half;
                unsigned w0 = mw0[ntile >> 2];
                unsigned w1 = mw1[ntile >> 2];
                int bitb = (ntile & 3) * 8 + (lane & 3) * 2;
                float p00 = exp2f(sacc[ntile][0]);
                float p01 = exp2f(sacc[ntile][1]);
                float p10 = exp2f(sacc[ntile][2]);
                float p11 = exp2f(sacc[ntile][3]);
                p00 = ((w0 >> bitb) & 1u) ? p00 : 0.f;
                p01 = ((w0 >> (bitb + 1)) & 1u) ? p01 : 0.f;
                p10 = ((w1 >> bitb) & 1u) ? p10 : 0.f;
                p11 = ((w1 >> (bitb + 1)) & 1u) ? p11 : 0.f;
                rs0 += p00 + p01;
                rs1 += p10 + p11;
                __nv_bfloat162 h0 = __floats2bfloat162_rn(p00, p01);
                __nv_bfloat162 h1 = __floats2bfloat162_rn(p10, p11);
                float2 hf0 = __bfloat1622float2(h0);
                float2 hf1 = __bfloat1622float2(h1);
                pf_hi[2 * half + 0] = *(unsigned*)&h0;
                pf_hi[2 * half + 1] = *(unsigned*)&h1;
                pf_lo[2 * half + 0] = pack_bf2(p00 - hf0.x, p01 - hf0.y);
                pf_lo[2 * half + 1] = pack_bf2(p10 - hf1.x, p11 - hf1.y);
            }
            unsigned va = smem_u32(Vs + (g0 + kk * 16 + (lane & 15)) *
                                            QKV_STRIDE +
                                   (lane >> 4) * 8);
            unsigned vh[4], vl[4];
            ldmx4t(vh, va);
            ldmx4t(vl, va + 32);
            mma16816(oacc[0], pf_hi, vh[0], vh[1]);
            mma16816(oacc[0], pf_hi, vl[0], vl[1]);
            mma16816(oacc[0], pf_lo, vh[0], vh[1]);
            mma16816(oacc[1], pf_hi, vh[2], vh[3]);
            mma16816(oacc[1], pf_hi, vl[2], vl[3]);
            mma16816(oacc[1], pf_lo, vh[2], vh[3]);
        }
    }

    rs0 += __shfl_xor_sync(0xffffffffu, rs0, 1);
    rs0 += __shfl_xor_sync(0xffffffffu, rs0, 2);
    rs1 += __shfl_xor_sync(0xffffffffu, rs1, 1);
    rs1 += __shfl_xor_sync(0xffffffffu, rs1, 2);
    float inv0 = __fdividef(1.0f, rs0);
    float inv1 = __fdividef(1.0f, rs1);

    const int d0 = (lane & 3) * 2;
    if (nr0 < Nn) {
        size_t base = ((size_t)(b * 512 + nr0)) * 256 + h * 16 + d0;
        float v0 = oacc[0][0] * inv0, v1 = oacc[0][1] * inv0;
        __nv_bfloat162 hh = __floats2bfloat162_rn(v0, v1);
        float2 hf = __bfloat1622float2(hh);
        *(unsigned*)(g_att_split + base) = *(unsigned*)&hh;
        *(unsigned*)(g_att_split + base + 128) =
            pack_bf2(v0 - hf.x, v1 - hf.y);
        v0 = oacc[1][0] * inv0; v1 = oacc[1][1] * inv0;
        hh = __floats2bfloat162_rn(v0, v1);
        hf = __bfloat1622float2(hh);
        *(unsigned*)(g_att_split + base + 8) = *(unsigned*)&hh;
        *(unsigned*)(g_att_split + base + 8 + 128) =
            pack_bf2(v0 - hf.x, v1 - hf.y);
    }
    if (nr1 < Nn) {
        size_t base = ((size_t)(b * 512 + nr1)) * 256 + h * 16 + d0;
        float v0 = oacc[0][2] * inv1, v1 = oacc[0][3] * inv1;
        __nv_bfloat162 hh = __floats2bfloat162_rn(v0, v1);
        float2 hf = __bfloat1622float2(hh);
        *(unsigned*)(g_att_split + base) = *(unsigned*)&hh;
        *(unsigned*)(g_att_split + base + 128) =
            pack_bf2(v0 - hf.x, v1 - hf.y);
        v0 = oacc[1][2] * inv1; v1 = oacc[1][3] * inv1;
        hh = __floats2bfloat162_rn(v0, v1);
        hf = __bfloat1622float2(hh);
        *(unsigned*)(g_att_split + base + 8) = *(unsigned*)&hh;
        *(unsigned*)(g_att_split + base + 8 + 128) =
            pack_bf2(v0 - hf.x, v1 - hf.y);
    }
}

// ---------------------------------------------------------------------------
// Launch 3: pointer v17 — v16 shape + fused combine prologue:
//   mh[128 rows] = att[128 rows] @ Wc^T + bc computed in-block, split into
//   As, then the v16 main loop runs unchanged.
// smem: As 128x264 + Bs 2x32x264 (doubles as 64x264 Wc buffer) + rsum[128].
// ---------------------------------------------------------------------------
#define AS_STRIDE 264
#define PTR_SMEM ((128 + 64) * AS_STRIDE * 2 + 512)

__global__ void __launch_bounds__(256, 2)
pointer_mma_kernel(const float* __restrict__ Wc, const float* __restrict__ bc,
                   float* __restrict__ out) {
    extern __shared__ char smem[];
    __nv_bfloat16* As = (__nv_bfloat16*)smem;                 // [128][264]
    __nv_bfloat16* Bs0 = As + 128 * AS_STRIDE;                // [32][264]
    __nv_bfloat16* Bs1 = Bs0 + 32 * AS_STRIDE;                // [32][264]
    __nv_bfloat16* Wt = Bs0;                                  // [64][264]
    float* rsum = (float*)(Bs1 + 32 * AS_STRIDE);             // [128]

    const int t = threadIdx.x;
    const int w = t >> 5, lane = t & 31;
    const int b = blockIdx.x >> 2;
    const int nt = blockIdx.x & 3;
    const int n0 = nt * 128;
    const int wrow = w * 16;          // each warp owns a unique 16-row stripe

    // ---- fused combine prologue ------------------------------------------
    // att rows -> As (cp.async); Wc chunk 0 -> Wt (inline split)
    {
        const uint4* src =
            (const uint4*)(g_att_split + ((size_t)(b * 512 + n0)) * 256);
        #pragma unroll
        for (int k = 0; k < 16; ++k) {
            int i4 = t + 256 * k;
            int row = i4 >> 5, c8 = i4 & 31;
            CP_ASYNC16(smem_u32(As + row * AS_STRIDE + c8 * 8), src + i4);
        }
        CP_COMMIT();
        #pragma unroll
        for (int k = 0; k < 8; ++k) {
            int i4 = t + 256 * k;
            int row = i4 >> 5, e4 = i4 & 31;
            float4 v = ((const float4*)Wc)[(size_t)row * 32 + e4];
            split_store(Wt + row * AS_STRIDE + e4 * 4, v);
        }
        CP_WAIT0();
    }
    __syncthreads();

    const unsigned arowb = wrow + (lane & 15);
    const unsigned kcolb = (lane >> 4) * 8;

    float macc[2][8][4];
    #pragma unroll
    for (int c = 0; c < 2; ++c)
        #pragma unroll
        for (int i = 0; i < 8; ++i)
            macc[c][i][0] = macc[c][i][1] = macc[c][i][2] = macc[c][i][3] = 0.f;

    #pragma unroll
    for (int chunk = 0; chunk < 2; ++chunk) {
        if (chunk == 1) {
            __syncthreads();   // chunk-0 Wt reads done
            #pragma unroll
            for (int k = 0; k < 8; ++k) {
                int i4 = t + 256 * k;
                int row = i4 >> 5, e4 = i4 & 31;
                float4 v = ((const float4*)Wc)[(size_t)(64 + row) * 32 + e4];
                split_store(Wt + row * AS_STRIDE + e4 * 4, v);
            }
            __syncthreads();
        }
        #pragma unroll
        for (int kk = 0; kk < 8; ++kk) {
            unsigned aaddr = smem_u32(As + arowb * AS_STRIDE + kcolb +
                                      kk * 16);
            unsigned ah[4], al[4];
            ldmx4(ah, aaddr);
            ldmx4(al, aaddr + 128 * 2);
            #pragma unroll
            for (int n16 = 0; n16 < 4; ++n16) {
                unsigned baddr = smem_u32(Wt + (n16 * 16 + (lane & 15)) *
                                              AS_STRIDE + kcolb + kk * 16);
                unsigned bh[4], bl[4];
                ldmx4(bh, baddr);
                ldmx4(bl, baddr + 128 * 2);
                mma16816(macc[chunk][2 * n16],     ah, bh[0], bh[2]);
                mma16816(macc[chunk][2 * n16 + 1], ah, bh[1], bh[3]);
                mma16816(macc[chunk][2 * n16],     ah, bl[0], bl[2]);
                mma16816(macc[chunk][2 * n16 + 1], ah, bl[1], bl[3]);
                mma16816(macc[chunk][2 * n16],     al, bh[0], bh[2]);
                mma16816(macc[chunk][2 * n16 + 1], al, bh[1], bh[3]);
            }
        }
    }
    __syncthreads();   // all att reads of As done; safe to overwrite

    // write mh (+bias) split into As
    {
        int r0 = wrow + (lane >> 2);
        int r1 = r0 + 8;
        #pragma unroll
        for (int chunk = 0; chunk < 2; ++chunk) {
            #pragma unroll
            for (int j = 0; j < 8; ++j) {
                int f = chunk * 64 + (j >> 1) * 16 + (j & 1) * 8 +
                        (lane & 3) * 2;
                float b0v = bc[f], b1v = bc[f + 1];
                float r00 = macc[chunk][j][0] + b0v;
                float r01 = macc[chunk][j][1] + b1v;
                float r10 = macc[chunk][j][2] + b0v;
                float r11 = macc[chunk][j][3] + b1v;
                __nv_bfloat162 h0 = __floats2bfloat162_rn(r00, r01);
                float2 ff0 = __bfloat1622float2(h0);
                unsigned lo0 = pack_bf2(r00 - ff0.x, r01 - ff0.y);
                __nv_bfloat162 h1 = __floats2bfloat162_rn(r10, r11);
                float2 ff1 = __bfloat1622float2(h1);
                unsigned lo1 = pack_bf2(r10 - ff1.x, r11 - ff1.y);
                *(unsigned*)(As + r0 * AS_STRIDE + f) = *(unsigned*)&h0;
                *(unsigned*)(As + r0 * AS_STRIDE + 128 + f) = lo0;
                *(unsigned*)(As + r1 * AS_STRIDE + f) = *(unsigned*)&h1;
                *(unsigned*)(As + r1 * AS_STRIDE + 128 + f) = lo1;
            }
        }
    }
    __syncthreads();

    // preload gt=0 B tile into Bs0 (Wt is dead now)
    {
        const uint4* bsrc =
            (const uint4*)(g_enc_split + ((size_t)(b * 512)) * 256);
        #pragma unroll
        for (int k = 0; k < 4; ++k) {
            int i4 = t + 256 * k;
            int row = i4 >> 5, c8 = i4 & 31;
            CP_ASYNC16(smem_u32(Bs0 + row * AS_STRIDE + c8 * 8), bsrc + i4);
        }
        CP_COMMIT();
        CP_WAIT0();
    }
    __syncthreads();

    // ---- main loop (v16, unchanged) ---------------------------------------
    const float C1 = 0.08838834764831845f * 2.0f * 1.4426950408889634f;
    const float C2 = 10.0f * 1.4426950408889634f;

    const int nr0 = n0 + wrow + (lane >> 2);
    const int nr1 = nr0 + 8;
    const int nr0c = (nr0 < Nn) ? nr0 : 0;
    const int nr1c = (nr1 < Nn) ? nr1 : 0;
    float rs0 = 0.f, rs1 = 0.f;

    for (int gt = 0; gt < 16; ++gt) {
        __nv_bfloat16* Bc = (gt & 1) ? Bs1 : Bs0;
        __nv_bfloat16* Bn = (gt & 1) ? Bs0 : Bs1;
        if (gt < 15) {
            const uint4* src = (const uint4*)(g_enc_split +
                ((size_t)(b * 512 + (gt + 1) * 32)) * 256);
            #pragma unroll
            for (int k = 0; k < 4; ++k) {
                int i4 = t + 256 * k;
                int row = i4 >> 5, c8 = i4 & 31;
                CP_ASYNC16(smem_u32(Bn + row * AS_STRIDE + c8 * 8), src + i4);
            }
            CP_COMMIT();
        }

        float acc[4][4];
        #pragma unroll
        for (int i = 0; i < 4; ++i)
            acc[i][0] = acc[i][1] = acc[i][2] = acc[i][3] = 0.f;

        #pragma unroll
        for (int kk = 0; kk < 8; ++kk) {
            unsigned aaddr = smem_u32(As + arowb * AS_STRIDE + kcolb +
                                      kk * 16);
            unsigned ah[4], al[4];
            ldmx4(ah, aaddr);
            ldmx4(al, aaddr + 128 * 2);
            #pragma unroll
            for (int n16 = 0; n16 < 2; ++n16) {
                unsigned baddr = smem_u32(Bc + (n16 * 16 + (lane & 15)) *
                                              AS_STRIDE + kcolb + kk * 16);
                unsigned bh[4], bl[4];
                ldmx4(bh, baddr);
                ldmx4(bl, baddr + 128 * 2);
                mma16816(acc[2 * n16],     ah, bh[0], bh[2]);
                mma16816(acc[2 * n16 + 1], ah, bh[1], bh[3]);
                mma16816(acc[2 * n16],     ah, bl[0], bl[2]);
                mma16816(acc[2 * n16 + 1], ah, bl[1], bl[3]);
                mma16816(acc[2 * n16],     al, bh[0], bh[2]);
                mma16816(acc[2 * n16 + 1], al, bh[1], bh[3]);
            }
        }

        const int g0 = gt * 32;
        unsigned w0 = g_maskbits[((size_t)b * Nn + nr0c) * 16 + gt];
        unsigned w1 = g_maskbits[((size_t)b * Nn + nr1c) * 16 + gt];

        #pragma unroll
        for (int j = 0; j < 4; ++j) {
            int bitb = j * 8 + (lane & 3) * 2;
            float p00, p01, p10, p11;
            {
                float u = exp2f(acc[j][0] * C1);
                p00 = exp2f(C2 * (1.0f - __fdividef(2.0f, u + 1.0f)));
            }
            {
                float u = exp2f(acc[j][1] * C1);
                p01 = exp2f(C2 * (1.0f - __fdividef(2.0f, u + 1.0f)));
            }
            {
                float u = exp2f(acc[j][2] * C1);
                p10 = exp2f(C2 * (1.0f - __fdividef(2.0f, u + 1.0f)));
            }
            {
                float u = exp2f(acc[j][3] * C1);
                p11 = exp2f(C2 * (1.0f - __fdividef(2.0f, u + 1.0f)));
            }
            p00 = ((w0 >> bitb) & 1u) ? p00 : 0.f;
            p01 = ((w0 >> (bitb + 1)) & 1u) ? p01 : 0.f;
            p10 = ((w1 >> bitb) & 1u) ? p10 : 0.f;
            p11 = ((w1 >> (bitb + 1)) & 1u) ? p11 : 0.f;
            rs0 += p00 + p01;
            rs1 += p10 + p11;
            int g = g0 + j * 8 + (lane & 3) * 2;
            if (g < Nn) {
                if (nr0 < Nn)
                    *(float2*)(out + ((size_t)b * Nn + nr0) * Nn + g) =
                        make_float2(p00, p01);
                if (nr1 < Nn)
                    *(float2*)(out + ((size_t)b * Nn + nr1) * Nn + g) =
                        make_float2(p10, p11);
            }
        }
        if (gt < 15) CP_WAIT0();
        __syncthreads();
    }

    rs0 += __shfl_xor_sync(0xffffffffu, rs0, 1);
    rs0 += __shfl_xor_sync(0xffffffffu, rs0, 2);
    rs1 += __shfl_xor_sync(0xffffffffu, rs1, 1);
    rs1 += __shfl_xor_sync(0xffffffffu, rs1, 2);
    if ((lane & 3) == 0) {
        rsum[wrow + (lane >> 2)] = rs0;
        rsum[wrow + (lane >> 2) + 8] = rs1;
    }
    __syncthreads();

    for (int i4 = t; i4 < 128 * 125; i4 += 256) {
        int row = i4 / 125, c4 = i4 - row * 125;
        int n = n0 + row;
        if (n < Nn) {
            float inv = __fdividef(1.0f, rsum[row]);
            float4* po = (float4*)(out + ((size_t)b * Nn + n) * Nn) + c4;
            float4 p = *po;
            p.x *= inv; p.y *= inv; p.z *= inv; p.w *= inv;
            *po = p;
        }
    }
}

// ---------------------------------------------------------------------------
// Launch
// ---------------------------------------------------------------------------
extern "C" void kernel_launch(void* const* d_in, const int* in_sizes, int n_in,
                              void* d_out, int out_size) {
    const float* enc_nodes = (const float*)d_in[0];
    const float* enc_first = (const float*)d_in[1];
    const float* enc_last  = (const float*)d_in[2];
    const float* mask      = (const float*)d_in[3];
    const float* Wq_first  = (const float*)d_in[4];
    const float* Wq_last   = (const float*)d_in[5];
    const float* Wk        = (const float*)d_in[6];
    const float* Wv        = (const float*)d_in[7];
    const float* Wc        = (const float*)d_in[8];
    const float* bc        = (const float*)d_in[9];
    float* out = (float*)d_out;

    static int configured = 0;
    if (!configured) {
        cudaFuncSetAttribute(qkv_prep_kernel,
            cudaFuncAttributeMaxDynamicSharedMemorySize, PRJ64_SMEM);
        cudaFuncSetAttribute(attn_mma_kernel,
            cudaFuncAttributeMaxDynamicSharedMemorySize, ATT_SMEM);
        cudaFuncSetAttribute(pointer_mma_kernel,
            cudaFuncAttributeMaxDynamicSharedMemorySize, PTR_SMEM);
        configured = 1;
    }

    // 1) qkv (inline fp32 splits) + enc split + maskbits
    qkv_prep_kernel<<<3314, 256, PRJ64_SMEM>>>(enc_nodes, enc_first, enc_last,
                                               mask, Wq_first, Wq_last,
                                               Wk, Wv);
    // 2) attention
    attn_mma_kernel<<<Bb * Hh * 4, 256, ATT_SMEM>>>();
    // 3) pointer with fused combine prologue
    pointer_mma_kernel<<<Bb * 4, 256, PTR_SMEM>>>(Wc, bc, out);

    (void)in_sizes; (void)n_in; (void)out_size;
}